// round 9
// baseline (speedup 1.0000x reference)
#include <cuda_runtime.h>
#include <float.h>

// Problem shape (fixed by the reference)
#define NB 32
#define NT 2048
#define ND 512

#define NC 8                  // chunks (blocks) per batch -> grid (32,8)=256
#define NW 16                 // warps per block (512 threads)
#define ROWS (NT / NC)        // 256 rows per block
#define RPW (ROWS / NW)       // 16 rows per warp
#define NSTATE (2 * NW)       // 2 softmax streams per warp

// Scratch (no cudaMalloc allowed)
__device__ __align__(16) float g_s_part[NB * NC * ND];           // 512 KB
__device__ float g_pm[NB * NC];
__device__ float g_pl[NB * NC];
__device__ __align__(16) float g_pacc[(size_t)NB * NC * ND];     // 512 KB
__device__ int g_cnt_s[NB];   // zero-init; reset by last block each launch
__device__ int g_cnt_p[NB];

__device__ __forceinline__ void f4add(float4& a, const float4 b) {
    a.x += b.x; a.y += b.y; a.z += b.z; a.w += b.w;
}

__device__ __forceinline__ float4 ldcs4(const float4* p) {
    return __ldcs(p);
}

// ---------------------------------------------------------------------------
// Fully fused (R8 structure) + two INDEPENDENT softmax streams per warp
// (alternating pairs) to halve the serial m/l chain and let consecutive
// pair-iterations overlap. Phase-2 global loads use __ldcs (evict-first)
// so the one-shot re-read doesn't evict yet-unread x lines from L2.
// All fold orders fixed -> bit-deterministic.
// ---------------------------------------------------------------------------
__global__ void __launch_bounds__(512, 2)
k_fused(const float* __restrict__ x, float* __restrict__ out) {
    const int b = blockIdx.x, c = blockIdx.y;
    const int tid = threadIdx.x, w = tid >> 5, lane = tid & 31;

    __shared__ float sm_m[NSTATE], sm_l[NSTATE];
    __shared__ int sm_last;
    __shared__ __align__(16) float sm_s[ND];             // 2 KB
    __shared__ __align__(16) float sm_acc[NSTATE][ND];   // 64 KB

    const float4* xb = (const float4*)(x + (size_t)b * NT * ND);
    const int tbase = c * ROWS + w;                   // rows: tbase + j*NW

    // ---- Phase 1: column-sum, 2 rows per iteration (8 loads in flight) ----
    float4 q0 = {0.f, 0.f, 0.f, 0.f}, q1 = q0, q2 = q0, q3 = q0;
    for (int j = 0; j < RPW; j += 2) {
        const float4* rA = xb + (size_t)(tbase + j * NW) * (ND / 4);
        const float4* rB = xb + (size_t)(tbase + (j + 1) * NW) * (ND / 4);
        const float4 a0 = rA[lane],      a1 = rA[32 + lane];
        const float4 a2 = rA[64 + lane], a3 = rA[96 + lane];
        const float4 b0 = rB[lane],      b1 = rB[32 + lane];
        const float4 b2 = rB[64 + lane], b3 = rB[96 + lane];
        f4add(q0, a0); f4add(q1, a1); f4add(q2, a2); f4add(q3, a3);
        f4add(q0, b0); f4add(q1, b1); f4add(q2, b2); f4add(q3, b3);
    }
    {
        float4* sa = (float4*)sm_acc[w];
        sa[lane] = q0; sa[32 + lane] = q1; sa[64 + lane] = q2; sa[96 + lane] = q3;
    }
    __syncthreads();
    if (tid < ND / 4) {
        float4 s = {0.f, 0.f, 0.f, 0.f};
        #pragma unroll
        for (int p = 0; p < NW; ++p) f4add(s, ((const float4*)sm_acc[p])[tid]);
        ((float4*)(g_s_part + (size_t)(b * NC + c) * ND))[tid] = s;
    }
    __threadfence();
    __syncthreads();

    // ---- Per-batch inter-block barrier (all 256 blocks co-resident) ----
    if (tid == 0) {
        atomicAdd(&g_cnt_s[b], 1);
        while (atomicAdd(&g_cnt_s[b], 0) < NC) __nanosleep(128);
    }
    __syncthreads();
    __threadfence();

    // ---- Zero BOTH stream accumulators; fold s-partials -> sm_s ----
    {
        float4 z = {0.f, 0.f, 0.f, 0.f};
        float4* sa0 = (float4*)sm_acc[w];
        float4* sa1 = (float4*)sm_acc[NW + w];
        sa0[lane] = z; sa0[32 + lane] = z; sa0[64 + lane] = z; sa0[96 + lane] = z;
        sa1[lane] = z; sa1[32 + lane] = z; sa1[64 + lane] = z; sa1[96 + lane] = z;
    }
    if (tid < ND / 4) {
        const float4* sp = (const float4*)(g_s_part + (size_t)b * NC * ND);
        float4 s = {0.f, 0.f, 0.f, 0.f};
        #pragma unroll
        for (int p = 0; p < NC; ++p) f4add(s, sp[p * (ND / 4) + tid]);
        ((float4*)sm_s)[tid] = s;
    }
    __syncthreads();
    const float4* sS = (const float4*)sm_s;
    float4* const acc0 = (float4*)sm_acc[w];        // stream 0 (warp-private)
    float4* const acc1 = (float4*)sm_acc[NW + w];   // stream 1 (warp-private)

    // ---- Phase 2: pairs of rows, descending; 2 alternating streams ----
    float m0 = -FLT_MAX, l0 = 0.f, m1 = -FLT_MAX, l1 = 0.f;

    #pragma unroll
    for (int pg = RPW / 2 - 1; pg >= 0; --pg) {
        const int j = 2 * pg;
        const float4* rA = xb + (size_t)(tbase + (j + 1) * NW) * (ND / 4);
        const float4* rB = xb + (size_t)(tbase + j * NW) * (ND / 4);
        const float4 v0 = ldcs4(rA + lane);
        const float4 v1 = ldcs4(rA + 32 + lane);
        const float4 v2 = ldcs4(rA + 64 + lane);
        const float4 v3 = ldcs4(rA + 96 + lane);
        const float4 u0 = ldcs4(rB + lane);
        const float4 u1 = ldcs4(rB + 32 + lane);
        const float4 u2 = ldcs4(rB + 64 + lane);
        const float4 u3 = ldcs4(rB + 96 + lane);

        // scores for both rows; s loaded once per quarter, shared
        float rAs, rBs;
        {
            const float4 s0 = sS[lane];
            rAs = v0.x * (s0.x - v0.x);
            rAs = fmaf(v0.y, s0.y - v0.y, rAs);
            rAs = fmaf(v0.z, s0.z - v0.z, rAs);
            rAs = fmaf(v0.w, s0.w - v0.w, rAs);
            rBs = u0.x * (s0.x - u0.x);
            rBs = fmaf(u0.y, s0.y - u0.y, rBs);
            rBs = fmaf(u0.z, s0.z - u0.z, rBs);
            rBs = fmaf(u0.w, s0.w - u0.w, rBs);
        }
        {
            const float4 s1 = sS[32 + lane];
            rAs = fmaf(v1.x, s1.x - v1.x, rAs);
            rAs = fmaf(v1.y, s1.y - v1.y, rAs);
            rAs = fmaf(v1.z, s1.z - v1.z, rAs);
            rAs = fmaf(v1.w, s1.w - v1.w, rAs);
            rBs = fmaf(u1.x, s1.x - u1.x, rBs);
            rBs = fmaf(u1.y, s1.y - u1.y, rBs);
            rBs = fmaf(u1.z, s1.z - u1.z, rBs);
            rBs = fmaf(u1.w, s1.w - u1.w, rBs);
        }
        {
            const float4 s2 = sS[64 + lane];
            rAs = fmaf(v2.x, s2.x - v2.x, rAs);
            rAs = fmaf(v2.y, s2.y - v2.y, rAs);
            rAs = fmaf(v2.z, s2.z - v2.z, rAs);
            rAs = fmaf(v2.w, s2.w - v2.w, rAs);
            rBs = fmaf(u2.x, s2.x - u2.x, rBs);
            rBs = fmaf(u2.y, s2.y - u2.y, rBs);
            rBs = fmaf(u2.z, s2.z - u2.z, rBs);
            rBs = fmaf(u2.w, s2.w - u2.w, rBs);
        }
        {
            const float4 s3 = sS[96 + lane];
            rAs = fmaf(v3.x, s3.x - v3.x, rAs);
            rAs = fmaf(v3.y, s3.y - v3.y, rAs);
            rAs = fmaf(v3.z, s3.z - v3.z, rAs);
            rAs = fmaf(v3.w, s3.w - v3.w, rAs);
            rBs = fmaf(u3.x, s3.x - u3.x, rBs);
            rBs = fmaf(u3.y, s3.y - u3.y, rBs);
            rBs = fmaf(u3.z, s3.z - u3.z, rBs);
            rBs = fmaf(u3.w, s3.w - u3.w, rBs);
        }

        // batched butterfly: both reductions in flight
        #pragma unroll
        for (int o = 16; o; o >>= 1) {
            rAs += __shfl_xor_sync(0xffffffffu, rAs, o);
            rBs += __shfl_xor_sync(0xffffffffu, rBs, o);
        }

        // select stream (compile-time after full unroll)
        float& m = (pg & 1) ? m1 : m0;
        float& l = (pg & 1) ? l1 : l0;
        float4* const acc = (pg & 1) ? acc1 : acc0;

        const float rmax = fmaxf(rAs, rBs);
        if (rmax > m) {
            const float sc = __expf(m - rmax);   // 0 on first pair of stream
            l *= sc;
            const float pA = __expf(rAs - rmax);
            const float pB = __expf(rBs - rmax);
            l += pA + pB;
            m = rmax;
            float4 A;
            A = acc[lane];
            A.x = fmaf(A.x, sc, fmaf(pA, v0.x, pB * u0.x));
            A.y = fmaf(A.y, sc, fmaf(pA, v0.y, pB * u0.y));
            A.z = fmaf(A.z, sc, fmaf(pA, v0.z, pB * u0.z));
            A.w = fmaf(A.w, sc, fmaf(pA, v0.w, pB * u0.w));
            acc[lane] = A;
            A = acc[32 + lane];
            A.x = fmaf(A.x, sc, fmaf(pA, v1.x, pB * u1.x));
            A.y = fmaf(A.y, sc, fmaf(pA, v1.y, pB * u1.y));
            A.z = fmaf(A.z, sc, fmaf(pA, v1.z, pB * u1.z));
            A.w = fmaf(A.w, sc, fmaf(pA, v1.w, pB * u1.w));
            acc[32 + lane] = A;
            A = acc[64 + lane];
            A.x = fmaf(A.x, sc, fmaf(pA, v2.x, pB * u2.x));
            A.y = fmaf(A.y, sc, fmaf(pA, v2.y, pB * u2.y));
            A.z = fmaf(A.z, sc, fmaf(pA, v2.z, pB * u2.z));
            A.w = fmaf(A.w, sc, fmaf(pA, v2.w, pB * u2.w));
            acc[64 + lane] = A;
            A = acc[96 + lane];
            A.x = fmaf(A.x, sc, fmaf(pA, v3.x, pB * u3.x));
            A.y = fmaf(A.y, sc, fmaf(pA, v3.y, pB * u3.y));
            A.z = fmaf(A.z, sc, fmaf(pA, v3.z, pB * u3.z));
            A.w = fmaf(A.w, sc, fmaf(pA, v3.w, pB * u3.w));
            acc[96 + lane] = A;
        } else {                           // common path: no rescale
            const float pA = __expf(rAs - m);
            const float pB = __expf(rBs - m);
            l += pA + pB;
            float4 A;
            A = acc[lane];
            A.x += fmaf(pA, v0.x, pB * u0.x);
            A.y += fmaf(pA, v0.y, pB * u0.y);
            A.z += fmaf(pA, v0.z, pB * u0.z);
            A.w += fmaf(pA, v0.w, pB * u0.w);
            acc[lane] = A;
            A = acc[32 + lane];
            A.x += fmaf(pA, v1.x, pB * u1.x);
            A.y += fmaf(pA, v1.y, pB * u1.y);
            A.z += fmaf(pA, v1.z, pB * u1.z);
            A.w += fmaf(pA, v1.w, pB * u1.w);
            acc[32 + lane] = A;
            A = acc[64 + lane];
            A.x += fmaf(pA, v2.x, pB * u2.x);
            A.y += fmaf(pA, v2.y, pB * u2.y);
            A.z += fmaf(pA, v2.z, pB * u2.z);
            A.w += fmaf(pA, v2.w, pB * u2.w);
            acc[64 + lane] = A;
            A = acc[96 + lane];
            A.x += fmaf(pA, v3.x, pB * u3.x);
            A.y += fmaf(pA, v3.y, pB * u3.y);
            A.z += fmaf(pA, v3.z, pB * u3.z);
            A.w += fmaf(pA, v3.w, pB * u3.w);
            acc[96 + lane] = A;
        }
    }

    // ---- In-block merge of 32 stream partials (already in sm_acc) ----
    if (lane == 0) {
        sm_m[w] = m0;      sm_l[w] = l0;
        sm_m[NW + w] = m1; sm_l[NW + w] = l1;
    }
    __syncthreads();
    if (tid < ND / 4) {
        float M = -FLT_MAX;
        #pragma unroll
        for (int p = 0; p < NSTATE; ++p) M = fmaxf(M, sm_m[p]);
        float L = 0.f;
        float4 o = {0.f, 0.f, 0.f, 0.f};
        #pragma unroll
        for (int p = 0; p < NSTATE; ++p) {
            const float e = __expf(sm_m[p] - M);
            L = fmaf(sm_l[p], e, L);
            const float4 a = ((const float4*)sm_acc[p])[tid];
            o.x = fmaf(e, a.x, o.x); o.y = fmaf(e, a.y, o.y);
            o.z = fmaf(e, a.z, o.z); o.w = fmaf(e, a.w, o.w);
        }
        const int pi = b * NC + c;
        if (tid == 0) { g_pm[pi] = M; g_pl[pi] = L; }
        ((float4*)(g_pacc + (size_t)pi * ND))[tid] = o;
    }
    __threadfence();
    __syncthreads();

    // ---- Last block per batch combines and writes output ----
    if (tid == 0) {
        const int old = atomicAdd(&g_cnt_p[b], 1);
        sm_last = (old == NC - 1);
    }
    __syncthreads();
    if (sm_last) {
        __threadfence();
        if (tid < ND / 4) {
            const float* pm = g_pm + b * NC;
            const float* pl = g_pl + b * NC;
            float M = -FLT_MAX;
            #pragma unroll
            for (int p = 0; p < NC; ++p) M = fmaxf(M, pm[p]);
            float L = 0.f;
            float4 o = {0.f, 0.f, 0.f, 0.f};
            #pragma unroll
            for (int p = 0; p < NC; ++p) {
                const float e = __expf(pm[p] - M);
                L = fmaf(pl[p], e, L);
                const float4 a =
                    ((const float4*)(g_pacc + (size_t)(b * NC + p) * ND))[tid];
                o.x = fmaf(e, a.x, o.x); o.y = fmaf(e, a.y, o.y);
                o.z = fmaf(e, a.z, o.z); o.w = fmaf(e, a.w, o.w);
            }
            const float inv = 1.f / L;
            o.x *= inv; o.y *= inv; o.z *= inv; o.w *= inv;
            ((float4*)(out + (size_t)b * ND))[tid] = o;
        }
        // reset counters for the next graph replay
        if (tid == 0) {
            atomicExch(&g_cnt_s[b], 0);
            atomicExch(&g_cnt_p[b], 0);
        }
    }
}

// ---------------------------------------------------------------------------
extern "C" void kernel_launch(void* const* d_in, const int* in_sizes, int n_in,
                              void* d_out, int out_size) {
    (void)in_sizes; (void)n_in; (void)out_size;
    const float* x = (const float*)d_in[0];
    float* out = (float*)d_out;

    k_fused<<<dim3(NB, NC), 512>>>(x, out);
}

// round 10
// speedup vs baseline: 1.0727x; 1.0727x over previous
#include <cuda_runtime.h>
#include <float.h>

// Problem shape (fixed by the reference)
#define NB 32
#define NT 2048
#define ND 512

#define NC 16                 // chunks (blocks) per batch -> grid (32,16)=512
#define NW 8                  // warps per block (256 threads)
#define ROWS (NT / NC)        // 128 rows per block
#define RPW (ROWS / NW)       // 16 rows per warp

// Scratch (no cudaMalloc allowed)
__device__ __align__(16) float g_s_part[NB * NC * ND];           // 1 MB
__device__ float g_pm[NB * NC];
__device__ float g_pl[NB * NC];
__device__ __align__(16) float g_pacc[(size_t)NB * NC * ND];     // 1 MB
__device__ int g_cnt_s[NB];   // zero-init; reset by last block each launch
__device__ int g_cnt_p[NB];

__device__ __forceinline__ void f4add(float4& a, const float4 b) {
    a.x += b.x; a.y += b.y; a.z += b.z; a.w += b.w;
}

// ---------------------------------------------------------------------------
// R8 structure (pairs of register-resident rows, SMEM warp accumulators,
// single online-softmax stream) re-packaged as 256-thread blocks at
// 4 blocks/SM: 512 blocks co-resident (592 slots), occupancy ceiling 64%.
// All fold orders fixed -> bit-deterministic.
// ---------------------------------------------------------------------------
__global__ void __launch_bounds__(256, 4)
k_fused(const float* __restrict__ x, float* __restrict__ out) {
    const int b = blockIdx.x, c = blockIdx.y;
    const int tid = threadIdx.x, w = tid >> 5, lane = tid & 31;

    __shared__ float sm_m[NW], sm_l[NW];
    __shared__ int sm_last;
    __shared__ __align__(16) float sm_s[ND];          // 2 KB
    __shared__ __align__(16) float sm_acc[NW][ND];    // 16 KB, reused twice

    const float4* xb = (const float4*)(x + (size_t)b * NT * ND);
    const int tbase = c * ROWS + w;                   // rows: tbase + j*NW

    // ---- Phase 1: column-sum, 2 rows per iteration (8 loads in flight) ----
    float4 q0 = {0.f, 0.f, 0.f, 0.f}, q1 = q0, q2 = q0, q3 = q0;
    for (int j = 0; j < RPW; j += 2) {
        const float4* rA = xb + (size_t)(tbase + j * NW) * (ND / 4);
        const float4* rB = xb + (size_t)(tbase + (j + 1) * NW) * (ND / 4);
        const float4 a0 = rA[lane],      a1 = rA[32 + lane];
        const float4 a2 = rA[64 + lane], a3 = rA[96 + lane];
        const float4 b0 = rB[lane],      b1 = rB[32 + lane];
        const float4 b2 = rB[64 + lane], b3 = rB[96 + lane];
        f4add(q0, a0); f4add(q1, a1); f4add(q2, a2); f4add(q3, a3);
        f4add(q0, b0); f4add(q1, b1); f4add(q2, b2); f4add(q3, b3);
    }
    {
        float4* sa = (float4*)sm_acc[w];
        sa[lane] = q0; sa[32 + lane] = q1; sa[64 + lane] = q2; sa[96 + lane] = q3;
    }
    __syncthreads();
    if (tid < ND / 4) {
        float4 s = {0.f, 0.f, 0.f, 0.f};
        #pragma unroll
        for (int p = 0; p < NW; ++p) f4add(s, ((const float4*)sm_acc[p])[tid]);
        ((float4*)(g_s_part + (size_t)(b * NC + c) * ND))[tid] = s;
    }
    __threadfence();
    __syncthreads();

    // ---- Per-batch inter-block barrier (all 512 blocks co-resident) ----
    if (tid == 0) {
        atomicAdd(&g_cnt_s[b], 1);
        while (atomicAdd(&g_cnt_s[b], 0) < NC) __nanosleep(128);
    }
    __syncthreads();
    __threadfence();

    // ---- Zero warp accumulators; fold the 16 s-partials -> sm_s ----
    {
        float4 z = {0.f, 0.f, 0.f, 0.f};
        float4* sa = (float4*)sm_acc[w];
        sa[lane] = z; sa[32 + lane] = z; sa[64 + lane] = z; sa[96 + lane] = z;
    }
    if (tid < ND / 4) {
        const float4* sp = (const float4*)(g_s_part + (size_t)b * NC * ND);
        float4 s = {0.f, 0.f, 0.f, 0.f};
        #pragma unroll
        for (int p = 0; p < NC; ++p) f4add(s, sp[p * (ND / 4) + tid]);
        ((float4*)sm_s)[tid] = s;
    }
    __syncthreads();
    const float4* sS = (const float4*)sm_s;
    float4* const myacc = (float4*)sm_acc[w];   // warp-private, no sync needed

    // ---- Phase 2: pairs of rows, descending order, single read of x ----
    float m = -FLT_MAX, l = 0.f;

    for (int j = RPW - 2; j >= 0; j -= 2) {
        const float4* rA = xb + (size_t)(tbase + (j + 1) * NW) * (ND / 4);
        const float4* rB = xb + (size_t)(tbase + j * NW) * (ND / 4);
        const float4 v0 = rA[lane];
        const float4 v1 = rA[32 + lane];
        const float4 v2 = rA[64 + lane];
        const float4 v3 = rA[96 + lane];
        const float4 u0 = rB[lane];
        const float4 u1 = rB[32 + lane];
        const float4 u2 = rB[64 + lane];
        const float4 u3 = rB[96 + lane];

        // scores for both rows; s loaded once per quarter, shared
        float rAs, rBs;
        {
            const float4 s0 = sS[lane];
            rAs = v0.x * (s0.x - v0.x);
            rAs = fmaf(v0.y, s0.y - v0.y, rAs);
            rAs = fmaf(v0.z, s0.z - v0.z, rAs);
            rAs = fmaf(v0.w, s0.w - v0.w, rAs);
            rBs = u0.x * (s0.x - u0.x);
            rBs = fmaf(u0.y, s0.y - u0.y, rBs);
            rBs = fmaf(u0.z, s0.z - u0.z, rBs);
            rBs = fmaf(u0.w, s0.w - u0.w, rBs);
        }
        {
            const float4 s1 = sS[32 + lane];
            rAs = fmaf(v1.x, s1.x - v1.x, rAs);
            rAs = fmaf(v1.y, s1.y - v1.y, rAs);
            rAs = fmaf(v1.z, s1.z - v1.z, rAs);
            rAs = fmaf(v1.w, s1.w - v1.w, rAs);
            rBs = fmaf(u1.x, s1.x - u1.x, rBs);
            rBs = fmaf(u1.y, s1.y - u1.y, rBs);
            rBs = fmaf(u1.z, s1.z - u1.z, rBs);
            rBs = fmaf(u1.w, s1.w - u1.w, rBs);
        }
        {
            const float4 s2 = sS[64 + lane];
            rAs = fmaf(v2.x, s2.x - v2.x, rAs);
            rAs = fmaf(v2.y, s2.y - v2.y, rAs);
            rAs = fmaf(v2.z, s2.z - v2.z, rAs);
            rAs = fmaf(v2.w, s2.w - v2.w, rAs);
            rBs = fmaf(u2.x, s2.x - u2.x, rBs);
            rBs = fmaf(u2.y, s2.y - u2.y, rBs);
            rBs = fmaf(u2.z, s2.z - u2.z, rBs);
            rBs = fmaf(u2.w, s2.w - u2.w, rBs);
        }
        {
            const float4 s3 = sS[96 + lane];
            rAs = fmaf(v3.x, s3.x - v3.x, rAs);
            rAs = fmaf(v3.y, s3.y - v3.y, rAs);
            rAs = fmaf(v3.z, s3.z - v3.z, rAs);
            rAs = fmaf(v3.w, s3.w - v3.w, rAs);
            rBs = fmaf(u3.x, s3.x - u3.x, rBs);
            rBs = fmaf(u3.y, s3.y - u3.y, rBs);
            rBs = fmaf(u3.z, s3.z - u3.z, rBs);
            rBs = fmaf(u3.w, s3.w - u3.w, rBs);
        }

        // batched butterfly: both reductions in flight
        #pragma unroll
        for (int o = 16; o; o >>= 1) {
            rAs += __shfl_xor_sync(0xffffffffu, rAs, o);
            rBs += __shfl_xor_sync(0xffffffffu, rBs, o);
        }

        // one m/l update per pair (warp-uniform branch)
        const float rmax = fmaxf(rAs, rBs);
        if (rmax > m) {
            const float sc = __expf(m - rmax);   // 0 on first pair
            l *= sc;
            const float pA = __expf(rAs - rmax);
            const float pB = __expf(rBs - rmax);
            l += pA + pB;
            m = rmax;
            float4 A;
            A = myacc[lane];
            A.x = fmaf(A.x, sc, fmaf(pA, v0.x, pB * u0.x));
            A.y = fmaf(A.y, sc, fmaf(pA, v0.y, pB * u0.y));
            A.z = fmaf(A.z, sc, fmaf(pA, v0.z, pB * u0.z));
            A.w = fmaf(A.w, sc, fmaf(pA, v0.w, pB * u0.w));
            myacc[lane] = A;
            A = myacc[32 + lane];
            A.x = fmaf(A.x, sc, fmaf(pA, v1.x, pB * u1.x));
            A.y = fmaf(A.y, sc, fmaf(pA, v1.y, pB * u1.y));
            A.z = fmaf(A.z, sc, fmaf(pA, v1.z, pB * u1.z));
            A.w = fmaf(A.w, sc, fmaf(pA, v1.w, pB * u1.w));
            myacc[32 + lane] = A;
            A = myacc[64 + lane];
            A.x = fmaf(A.x, sc, fmaf(pA, v2.x, pB * u2.x));
            A.y = fmaf(A.y, sc, fmaf(pA, v2.y, pB * u2.y));
            A.z = fmaf(A.z, sc, fmaf(pA, v2.z, pB * u2.z));
            A.w = fmaf(A.w, sc, fmaf(pA, v2.w, pB * u2.w));
            myacc[64 + lane] = A;
            A = myacc[96 + lane];
            A.x = fmaf(A.x, sc, fmaf(pA, v3.x, pB * u3.x));
            A.y = fmaf(A.y, sc, fmaf(pA, v3.y, pB * u3.y));
            A.z = fmaf(A.z, sc, fmaf(pA, v3.z, pB * u3.z));
            A.w = fmaf(A.w, sc, fmaf(pA, v3.w, pB * u3.w));
            myacc[96 + lane] = A;
        } else {                           // common path: no rescale
            const float pA = __expf(rAs - m);
            const float pB = __expf(rBs - m);
            l += pA + pB;
            float4 A;
            A = myacc[lane];
            A.x += fmaf(pA, v0.x, pB * u0.x);
            A.y += fmaf(pA, v0.y, pB * u0.y);
            A.z += fmaf(pA, v0.z, pB * u0.z);
            A.w += fmaf(pA, v0.w, pB * u0.w);
            myacc[lane] = A;
            A = myacc[32 + lane];
            A.x += fmaf(pA, v1.x, pB * u1.x);
            A.y += fmaf(pA, v1.y, pB * u1.y);
            A.z += fmaf(pA, v1.z, pB * u1.z);
            A.w += fmaf(pA, v1.w, pB * u1.w);
            myacc[32 + lane] = A;
            A = myacc[64 + lane];
            A.x += fmaf(pA, v2.x, pB * u2.x);
            A.y += fmaf(pA, v2.y, pB * u2.y);
            A.z += fmaf(pA, v2.z, pB * u2.z);
            A.w += fmaf(pA, v2.w, pB * u2.w);
            myacc[64 + lane] = A;
            A = myacc[96 + lane];
            A.x += fmaf(pA, v3.x, pB * u3.x);
            A.y += fmaf(pA, v3.y, pB * u3.y);
            A.z += fmaf(pA, v3.z, pB * u3.z);
            A.w += fmaf(pA, v3.w, pB * u3.w);
            myacc[96 + lane] = A;
        }
    }

    // ---- In-block merge of 8 warp partials (already in sm_acc) ----
    if (lane == 0) { sm_m[w] = m; sm_l[w] = l; }
    __syncthreads();
    if (tid < ND / 4) {
        float M = -FLT_MAX;
        #pragma unroll
        for (int p = 0; p < NW; ++p) M = fmaxf(M, sm_m[p]);
        float L = 0.f;
        float4 o = {0.f, 0.f, 0.f, 0.f};
        #pragma unroll
        for (int p = 0; p < NW; ++p) {
            const float e = __expf(sm_m[p] - M);
            L = fmaf(sm_l[p], e, L);
            const float4 a = ((const float4*)sm_acc[p])[tid];
            o.x = fmaf(e, a.x, o.x); o.y = fmaf(e, a.y, o.y);
            o.z = fmaf(e, a.z, o.z); o.w = fmaf(e, a.w, o.w);
        }
        const int pi = b * NC + c;
        if (tid == 0) { g_pm[pi] = M; g_pl[pi] = L; }
        ((float4*)(g_pacc + (size_t)pi * ND))[tid] = o;
    }
    __threadfence();
    __syncthreads();

    // ---- Last block per batch combines and writes output ----
    if (tid == 0) {
        const int old = atomicAdd(&g_cnt_p[b], 1);
        sm_last = (old == NC - 1);
    }
    __syncthreads();
    if (sm_last) {
        __threadfence();
        if (tid < ND / 4) {
            const float* pm = g_pm + b * NC;
            const float* pl = g_pl + b * NC;
            float M = -FLT_MAX;
            #pragma unroll
            for (int p = 0; p < NC; ++p) M = fmaxf(M, pm[p]);
            float L = 0.f;
            float4 o = {0.f, 0.f, 0.f, 0.f};
            #pragma unroll
            for (int p = 0; p < NC; ++p) {
                const float e = __expf(pm[p] - M);
                L = fmaf(pl[p], e, L);
                const float4 a =
                    ((const float4*)(g_pacc + (size_t)(b * NC + p) * ND))[tid];
                o.x = fmaf(e, a.x, o.x); o.y = fmaf(e, a.y, o.y);
                o.z = fmaf(e, a.z, o.z); o.w = fmaf(e, a.w, o.w);
            }
            const float inv = 1.f / L;
            o.x *= inv; o.y *= inv; o.z *= inv; o.w *= inv;
            ((float4*)(out + (size_t)b * ND))[tid] = o;
        }
        // reset counters for the next graph replay
        if (tid == 0) {
            atomicExch(&g_cnt_s[b], 0);
            atomicExch(&g_cnt_p[b], 0);
        }
    }
}

// ---------------------------------------------------------------------------
extern "C" void kernel_launch(void* const* d_in, const int* in_sizes, int n_in,
                              void* d_out, int out_size) {
    (void)in_sizes; (void)n_in; (void)out_size;
    const float* x = (const float*)d_in[0];
    float* out = (float*)d_out;

    k_fused<<<dim3(NB, NC), 256>>>(x, out);
}